// round 12
// baseline (speedup 1.0000x reference)
#include <cuda_runtime.h>
#include <cuda_bf16.h>
#include <cstdint>
#include <cstdio>

// Problem sizes
#define TOK   16384
#define DDIM  768
#define FDIM  3072
#define NEXP  8
#define BM    128
#define MAXTILES 136
#define PADT  (MAXTILES * BM)
#define OUT0  ((size_t)TOK * DDIM)
#define OUT1  (OUT0 + (size_t)TOK * NEXP)

// mma GEMM tiling: 128x128 tile, BK=32 per stage, single buffer (static smem)
#define BK      32
#define ROWB    80
#define TILE_B  (128 * ROWB)
#define SMEM_T  (4 * TILE_B)

// ---------------- scratch (device globals) -----------------------------------
__device__ float g_top_prob[TOK];
__device__ int   g_expert[TOK];
__device__ int   g_counts[NEXP];
__device__ int   g_counts2[NEXP];
__device__ int   g_padoff[NEXP];
__device__ int   g_ntiles;
__device__ int   g_perm[PADT];
__device__ int   g_tile_expert[MAXTILES];
__device__ float g_diag[4];

__device__ __align__(16) __nv_bfloat16 g_xhi[(size_t)TOK * DDIM];
__device__ __align__(16) __nv_bfloat16 g_xlo[(size_t)TOK * DDIM];
__device__ __align__(16) __nv_bfloat16 g_w1hi[(size_t)NEXP * FDIM * DDIM]; // [e][f][d]
__device__ __align__(16) __nv_bfloat16 g_w1lo[(size_t)NEXP * FDIM * DDIM];
__device__ __align__(16) __nv_bfloat16 g_w2hi[(size_t)NEXP * DDIM * FDIM]; // [e][d][f]
__device__ __align__(16) __nv_bfloat16 g_w2lo[(size_t)NEXP * DDIM * FDIM];
__device__ __align__(16) __nv_bfloat16 g_hhi[(size_t)PADT * FDIM];
__device__ __align__(16) __nv_bfloat16 g_hlo[(size_t)PADT * FDIM];
__device__ float g_hidden[(size_t)PADT * FDIM];       // SIMT reference H
__device__ float g_out_mma[(size_t)TOK * DDIM];       // mma pipeline out (scratch)

// ---------------- PTX helpers -------------------------------------------------
__device__ __forceinline__ uint32_t smem_u32(const void* p) {
    uint32_t a;
    asm("{ .reg .u64 t; cvta.to.shared.u64 t, %1; cvt.u32.u64 %0, t; }" : "=r"(a) : "l"(p));
    return a;
}
#define LDS32(v, addr) \
    asm volatile("ld.shared.b32 %0, [%1];" : "=r"(v) : "r"(addr))
#define MMA_BF16(C, A, B0, B1) \
    asm volatile("mma.sync.aligned.m16n8k16.row.col.f32.bf16.bf16.f32 " \
        "{%0,%1,%2,%3}, {%4,%5,%6,%7}, {%8,%9}, {%0,%1,%2,%3};" \
        : "+f"((C)[0]), "+f"((C)[1]), "+f"((C)[2]), "+f"((C)[3]) \
        : "r"((A)[0]), "r"((A)[1]), "r"((A)[2]), "r"((A)[3]), "r"(B0), "r"(B1))

__device__ __forceinline__ uint32_t pack_bf16(float a, float b) {
    __nv_bfloat16 ha = __float2bfloat16(a), hb = __float2bfloat16(b);
    return ((uint32_t)__bfloat16_as_ushort(hb) << 16) | __bfloat16_as_ushort(ha);
}
__device__ __forceinline__ void atomic_fmax(float* p, float v) {
    atomicMax((int*)p, __float_as_int(v));   // v >= 0
}

// ---------------- small kernels ----------------------------------------------
__global__ void reset_kernel() {
    int t = threadIdx.x;
    if (t < NEXP) { g_counts[t] = 0; g_counts2[t] = 0; }
    if (t < 4) g_diag[t] = 0.f;
}

__global__ void router_kernel(const float* __restrict__ x,
                              const float* __restrict__ rw,
                              float* __restrict__ out, int aux) {
    int w    = (blockIdx.x * blockDim.x + threadIdx.x) >> 5;
    int lane = threadIdx.x & 31;
    if (w >= TOK) return;
    const float* xr = x + (size_t)w * DDIM;
    float acc[NEXP];
#pragma unroll
    for (int e = 0; e < NEXP; e++) acc[e] = 0.f;
    for (int d = lane; d < DDIM; d += 32) {
        float xv = xr[d];
        const float* r = rw + d * NEXP;
#pragma unroll
        for (int e = 0; e < NEXP; e++) acc[e] = fmaf(xv, r[e], acc[e]);
    }
#pragma unroll
    for (int e = 0; e < NEXP; e++)
#pragma unroll
        for (int o = 16; o; o >>= 1) acc[e] += __shfl_xor_sync(0xffffffffu, acc[e], o);
    if (lane == 0) {
        float m = acc[0]; int be = 0;
#pragma unroll
        for (int e = 1; e < NEXP; e++) if (acc[e] > m) { m = acc[e]; be = e; }
        float s = 0.f;
#pragma unroll
        for (int e = 0; e < NEXP; e++) s += expf(acc[e] - m);
        g_expert[w]   = be;
        g_top_prob[w] = 1.f / s;
        atomicAdd(&g_counts[be], 1);
        if (aux) {
            float* lg = out + OUT0 + (size_t)w * NEXP;
#pragma unroll
            for (int e = 0; e < NEXP; e++) lg[e] = acc[e];
            out[OUT1 + w] = (float)be;
        }
    }
}

__global__ void build_kernel() {
    int t = threadIdx.x;
    for (int i = t; i < PADT; i += blockDim.x) g_perm[i] = -1;
    __syncthreads();
    if (t == 0) {
        int off = 0, tile = 0;
        for (int e = 0; e < NEXP; e++) {
            g_padoff[e] = off;
            int nt = (g_counts[e] + BM - 1) / BM;
            for (int i = 0; i < nt; i++) g_tile_expert[tile++] = e;
            off += nt * BM;
        }
        g_ntiles = tile;
    }
}

__global__ void scatter_kernel() {
    int t = blockIdx.x * blockDim.x + threadIdx.x;
    if (t < TOK) {
        int e = g_expert[t];
        int pos = atomicAdd(&g_counts2[e], 1);
        g_perm[g_padoff[e] + pos] = t;
    }
}

// ---------------- conversion prepass -----------------------------------------
__global__ void conv_x_kernel(const float* __restrict__ x) {
    size_t i = (size_t)blockIdx.x * blockDim.x + threadIdx.x;
    size_t n4 = (size_t)TOK * DDIM / 4;
    if (i >= n4) return;
    float4 v = ((const float4*)x)[i];
    __nv_bfloat16 h0 = __float2bfloat16(v.x), h1 = __float2bfloat16(v.y);
    __nv_bfloat16 h2 = __float2bfloat16(v.z), h3 = __float2bfloat16(v.w);
    uint2 hp, lp;
    hp.x = ((uint32_t)__bfloat16_as_ushort(h1) << 16) | __bfloat16_as_ushort(h0);
    hp.y = ((uint32_t)__bfloat16_as_ushort(h3) << 16) | __bfloat16_as_ushort(h2);
    lp.x = pack_bf16(v.x - __bfloat162float(h0), v.y - __bfloat162float(h1));
    lp.y = pack_bf16(v.z - __bfloat162float(h2), v.w - __bfloat162float(h3));
    ((uint2*)g_xhi)[i] = hp;
    ((uint2*)g_xlo)[i] = lp;
}

__global__ void conv_wt_kernel(const float* __restrict__ w,
                               __nv_bfloat16* __restrict__ hi,
                               __nv_bfloat16* __restrict__ lo, int R, int C) {
    __shared__ float t[32][33];
    int e  = blockIdx.z;
    int r0 = blockIdx.y * 32, c0 = blockIdx.x * 32;
    int tx = threadIdx.x, ty = threadIdx.y;
    const float* we = w + (size_t)e * R * C;
#pragma unroll
    for (int i = 0; i < 32; i += 8)
        t[ty + i][tx] = we[(size_t)(r0 + ty + i) * C + c0 + tx];
    __syncthreads();
    size_t ob = (size_t)e * R * C;
#pragma unroll
    for (int i = 0; i < 32; i += 8) {
        float v = t[tx][ty + i];
        __nv_bfloat16 h = __float2bfloat16(v);
        size_t o = ob + (size_t)(c0 + ty + i) * R + r0 + tx;
        hi[o] = h;
        lo[o] = __float2bfloat16(v - __bfloat162float(h));
    }
}

// ---------------- mma GEMM core ----------------------------------------------
__device__ __forceinline__ void compute_stage(uint32_t sb, int lane,
                                              int wm, int wn, float acc[2][8][4]) {
    int r4 = lane >> 2, kc = (lane & 3) * 2;
#pragma unroll
    for (int ks = 0; ks < 2; ks++) {
        int kb = ks * 32 + kc * 2;
        uint32_t ah[2][4], al[2][4];
#pragma unroll
        for (int mt = 0; mt < 2; mt++) {
            uint32_t a0 = sb + (uint32_t)(wm + mt * 16 + r4) * ROWB + kb;
            LDS32(ah[mt][0], a0);
            LDS32(ah[mt][1], a0 + 8 * ROWB);
            LDS32(ah[mt][2], a0 + 16);
            LDS32(ah[mt][3], a0 + 8 * ROWB + 16);
            uint32_t a1 = a0 + TILE_B;
            LDS32(al[mt][0], a1);
            LDS32(al[mt][1], a1 + 8 * ROWB);
            LDS32(al[mt][2], a1 + 16);
            LDS32(al[mt][3], a1 + 8 * ROWB + 16);
        }
        uint32_t bh[8][2], bl[8][2];
#pragma unroll
        for (int g = 0; g < 8; g++) {
            uint32_t b0 = sb + 2 * TILE_B + (uint32_t)(wn + g * 8 + r4) * ROWB + kb;
            LDS32(bh[g][0], b0);
            LDS32(bh[g][1], b0 + 16);
            uint32_t b1 = b0 + TILE_B;
            LDS32(bl[g][0], b1);
            LDS32(bl[g][1], b1 + 16);
        }
#pragma unroll
        for (int mt = 0; mt < 2; mt++)
#pragma unroll
            for (int g = 0; g < 8; g++) {
                MMA_BF16(acc[mt][g], ah[mt], bh[g][0], bh[g][1]);
                MMA_BF16(acc[mt][g], ah[mt], bl[g][0], bl[g][1]);
                MMA_BF16(acc[mt][g], al[mt], bh[g][0], bh[g][1]);
            }
    }
}

__global__ __launch_bounds__(256, 1) void gemm1_mma() {
    int tm = blockIdx.y; if (tm >= g_ntiles) return;
    int tn = blockIdx.x;
    int e  = g_tile_expert[tm];

    __shared__ __align__(16) char sp[SMEM_T];
    __shared__ int s_tok[128];
    uint32_t sb = smem_u32(sp);
    int tid = threadIdx.x, lane = tid & 31, wid = tid >> 5;
    int wm = (wid & 3) * 32, wn = (wid >> 2) * 64;

    if (tid < 128) s_tok[tid] = g_perm[tm * 128 + tid];
    __syncthreads();

    const char* srcp[8];
    char* dstp[8];
    int zero[8];
#pragma unroll
    for (int j = 0; j < 8; j++) {
        int gid = j * 256 + tid;
        int tile = gid >> 9, id = gid & 511, r = id >> 2, c = id & 3;
        dstp[j] = sp + tile * TILE_B + r * ROWB + c * 16;
        zero[j] = 0;
        if (tile < 2) {
            int tok = s_tok[r];
            if (tok < 0) { zero[j] = 1; srcp[j] = (const char*)g_xhi; }
            else srcp[j] = (const char*)((tile ? g_xlo : g_xhi) + (size_t)tok * DDIM) + c * 16;
        } else {
            size_t row = (size_t)e * FDIM + (size_t)tn * 128 + r;
            srcp[j] = (const char*)((tile == 2 ? g_w1hi : g_w1lo) + row * DDIM) + c * 16;
        }
    }

    float acc[2][8][4];
#pragma unroll
    for (int mt = 0; mt < 2; mt++)
#pragma unroll
        for (int g = 0; g < 8; g++)
#pragma unroll
            for (int k = 0; k < 4; k++) acc[mt][g][k] = 0.f;

    const int NST = DDIM / BK;
    for (int s = 0; s < NST; s++) {
        __syncthreads();
#pragma unroll
        for (int j = 0; j < 8; j++) {
            uint4 v = zero[j] ? make_uint4(0, 0, 0, 0)
                              : *(const uint4*)(srcp[j] + (size_t)s * (BK * 2));
            *(uint4*)dstp[j] = v;
        }
        __syncthreads();
        compute_stage(sb, lane, wm, wn, acc);
    }

    int lr = lane >> 2, lc = (lane & 3) * 2;
#pragma unroll
    for (int mt = 0; mt < 2; mt++) {
        size_t row0 = (size_t)(tm * 128 + wm + mt * 16 + lr);
#pragma unroll
        for (int g = 0; g < 8; g++) {
            float* a = acc[mt][g];
            int col = tn * 128 + wn + g * 8 + lc;
            float v0 = fmaxf(a[0], 0.f), v1 = fmaxf(a[1], 0.f);
            float v2 = fmaxf(a[2], 0.f), v3 = fmaxf(a[3], 0.f);
            size_t o0 = row0 * FDIM + col;
            size_t o1 = o0 + 8 * FDIM;
            uint32_t h0 = pack_bf16(v0, v1), h1 = pack_bf16(v2, v3);
            *(uint32_t*)(g_hhi + o0) = h0;
            *(uint32_t*)(g_hhi + o1) = h1;
            float r0a = v0 - __bfloat162float(__ushort_as_bfloat16((unsigned short)(h0 & 0xffff)));
            float r0b = v1 - __bfloat162float(__ushort_as_bfloat16((unsigned short)(h0 >> 16)));
            float r1a = v2 - __bfloat162float(__ushort_as_bfloat16((unsigned short)(h1 & 0xffff)));
            float r1b = v3 - __bfloat162float(__ushort_as_bfloat16((unsigned short)(h1 >> 16)));
            *(uint32_t*)(g_hlo + o0) = pack_bf16(r0a, r0b);
            *(uint32_t*)(g_hlo + o1) = pack_bf16(r1a, r1b);
        }
    }
}

__global__ __launch_bounds__(256, 1) void gemm2_mma(float* __restrict__ outb) {
    int tm = blockIdx.y; if (tm >= g_ntiles) return;
    int tn = blockIdx.x;
    int e  = g_tile_expert[tm];

    __shared__ __align__(16) char sp[SMEM_T];
    uint32_t sb = smem_u32(sp);
    int tid = threadIdx.x, lane = tid & 31, wid = tid >> 5;
    int wm = (wid & 3) * 32, wn = (wid >> 2) * 64;

    const char* srcp[8];
    char* dstp[8];
#pragma unroll
    for (int j = 0; j < 8; j++) {
        int gid = j * 256 + tid;
        int tile = gid >> 9, id = gid & 511, r = id >> 2, c = id & 3;
        dstp[j] = sp + tile * TILE_B + r * ROWB + c * 16;
        if (tile < 2) {
            size_t row = (size_t)(tm * 128 + r);
            srcp[j] = (const char*)((tile ? g_hlo : g_hhi) + row * FDIM) + c * 16;
        } else {
            size_t row = (size_t)e * DDIM + (size_t)tn * 128 + r;
            srcp[j] = (const char*)((tile == 2 ? g_w2hi : g_w2lo) + row * FDIM) + c * 16;
        }
    }

    float acc[2][8][4];
#pragma unroll
    for (int mt = 0; mt < 2; mt++)
#pragma unroll
        for (int g = 0; g < 8; g++)
#pragma unroll
            for (int k = 0; k < 4; k++) acc[mt][g][k] = 0.f;

    const int NST = FDIM / BK;
    for (int s = 0; s < NST; s++) {
        __syncthreads();
#pragma unroll
        for (int j = 0; j < 8; j++)
            *(uint4*)dstp[j] = *(const uint4*)(srcp[j] + (size_t)s * (BK * 2));
        __syncthreads();
        compute_stage(sb, lane, wm, wn, acc);
    }

    int lr = lane >> 2, lc = (lane & 3) * 2;
#pragma unroll
    for (int mt = 0; mt < 2; mt++) {
        int prow = tm * 128 + wm + mt * 16 + lr;
        int tok0 = g_perm[prow];
        int tok1 = g_perm[prow + 8];
        float p0 = (tok0 >= 0) ? g_top_prob[tok0] : 0.f;
        float p1 = (tok1 >= 0) ? g_top_prob[tok1] : 0.f;
#pragma unroll
        for (int g = 0; g < 8; g++) {
            float* a = acc[mt][g];
            int col = tn * 128 + wn + g * 8 + lc;
            if (tok0 >= 0) {
                float2 v = make_float2(a[0] * p0, a[1] * p0);
                *(float2*)(outb + (size_t)tok0 * DDIM + col) = v;
            }
            if (tok1 >= 0) {
                float2 v = make_float2(a[2] * p1, a[3] * p1);
                *(float2*)(outb + (size_t)tok1 * DDIM + col) = v;
            }
        }
    }
}

// ---------------- known-good fp32 SIMT GEMMs (R2) -----------------------------
__global__ __launch_bounds__(256, 2)
void gemm1_f32(const float* __restrict__ x, const float* __restrict__ w_in) {
    int tm = blockIdx.y; if (tm >= g_ntiles) return;
    int tn = blockIdx.x;
    int e  = g_tile_expert[tm];
    const float* Bg = w_in + (size_t)e * DDIM * FDIM + (size_t)tn * 128;

    __shared__ float As[8][128];
    __shared__ float Bs[8][128];

    int tid  = threadIdx.x;
    int arow = tid >> 1;
    int ak   = (tid & 1) * 4;
    int token = g_perm[tm * BM + arow];
    const float* Ag = (token >= 0) ? (x + (size_t)token * DDIM + ak) : nullptr;
    int bk = tid >> 5;
    int bn = (tid & 31) * 4;
    const float* Bgp = Bg + (size_t)bk * FDIM + bn;

    float acc[8][8];
#pragma unroll
    for (int i = 0; i < 8; i++)
#pragma unroll
        for (int j = 0; j < 8; j++) acc[i][j] = 0.f;

    int ty = (tid >> 4) * 8;
    int tx = (tid & 15) * 8;

    for (int k0 = 0; k0 < DDIM; k0 += 8) {
        float4 av = Ag ? *(const float4*)(Ag + k0) : make_float4(0.f, 0.f, 0.f, 0.f);
        As[ak + 0][arow] = av.x; As[ak + 1][arow] = av.y;
        As[ak + 2][arow] = av.z; As[ak + 3][arow] = av.w;
        float4 bv = *(const float4*)(Bgp + (size_t)k0 * FDIM);
        *(float4*)&Bs[bk][bn] = bv;
        __syncthreads();
#pragma unroll
        for (int k = 0; k < 8; k++) {
            float4 a0 = *(float4*)&As[k][ty], a1 = *(float4*)&As[k][ty + 4];
            float4 b0 = *(float4*)&Bs[k][tx], b1 = *(float4*)&Bs[k][tx + 4];
            float a[8] = {a0.x, a0.y, a0.z, a0.w, a1.x, a1.y, a1.z, a1.w};
            float b[8] = {b0.x, b0.y, b0.z, b0.w, b1.x, b1.y, b1.z, b1.w};
#pragma unroll
            for (int i = 0; i < 8; i++)
#pragma unroll
                for (int j = 0; j < 8; j++) acc[i][j] = fmaf(a[i], b[j], acc[i][j]);
        }
        __syncthreads();
    }

    float* Hp = g_hidden + (size_t)(tm * BM) * FDIM + (size_t)tn * 128;
#pragma unroll
    for (int i = 0; i < 8; i++) {
        float4 v0, v1;
        v0.x = fmaxf(acc[i][0], 0.f); v0.y = fmaxf(acc[i][1], 0.f);
        v0.z = fmaxf(acc[i][2], 0.f); v0.w = fmaxf(acc[i][3], 0.f);
        v1.x = fmaxf(acc[i][4], 0.f); v1.y = fmaxf(acc[i][5], 0.f);
        v1.z = fmaxf(acc[i][6], 0.f); v1.w = fmaxf(acc[i][7], 0.f);
        *(float4*)&Hp[(size_t)(ty + i) * FDIM + tx]     = v0;
        *(float4*)&Hp[(size_t)(ty + i) * FDIM + tx + 4] = v1;
    }
}

__global__ __launch_bounds__(256, 2)
void gemm2_f32(const float* __restrict__ w_out, float* __restrict__ out) {
    int tm = blockIdx.y; if (tm >= g_ntiles) return;
    int tn = blockIdx.x;
    int e  = g_tile_expert[tm];
    const float* Bg = w_out + (size_t)e * FDIM * DDIM + (size_t)tn * 128;

    __shared__ float As[8][128];
    __shared__ float Bs[8][128];

    int tid  = threadIdx.x;
    int arow = tid >> 1;
    int ak   = (tid & 1) * 4;
    const float* Ag = g_hidden + (size_t)(tm * BM + arow) * FDIM + ak;
    int bk = tid >> 5;
    int bn = (tid & 31) * 4;
    const float* Bgp = Bg + (size_t)bk * DDIM + bn;

    float acc[8][8];
#pragma unroll
    for (int i = 0; i < 8; i++)
#pragma unroll
        for (int j = 0; j < 8; j++) acc[i][j] = 0.f;

    int ty = (tid >> 4) * 8;
    int tx = (tid & 15) * 8;

    for (int k0 = 0; k0 < FDIM; k0 += 8) {
        float4 av = *(const float4*)(Ag + k0);
        As[ak + 0][arow] = av.x; As[ak + 1][arow] = av.y;
        As[ak + 2][arow] = av.z; As[ak + 3][arow] = av.w;
        float4 bv = *(const float4*)(Bgp + (size_t)k0 * DDIM);
        *(float4*)&Bs[bk][bn] = bv;
        __syncthreads();
#pragma unroll
        for (int k = 0; k < 8; k++) {
            float4 a0 = *(float4*)&As[k][ty], a1 = *(float4*)&As[k][ty + 4];
            float4 b0 = *(float4*)&Bs[k][tx], b1 = *(float4*)&Bs[k][tx + 4];
            float a[8] = {a0.x, a0.y, a0.z, a0.w, a1.x, a1.y, a1.z, a1.w};
            float b[8] = {b0.x, b0.y, b0.z, b0.w, b1.x, b1.y, b1.z, b1.w};
#pragma unroll
            for (int i = 0; i < 8; i++)
#pragma unroll
                for (int j = 0; j < 8; j++) acc[i][j] = fmaf(a[i], b[j], acc[i][j]);
        }
        __syncthreads();
    }

#pragma unroll
    for (int i = 0; i < 8; i++) {
        int token = g_perm[tm * BM + ty + i];
        if (token < 0) continue;
        float p = g_top_prob[token];
        float4 v0, v1;
        v0.x = acc[i][0] * p; v0.y = acc[i][1] * p;
        v0.z = acc[i][2] * p; v0.w = acc[i][3] * p;
        v1.x = acc[i][4] * p; v1.y = acc[i][5] * p;
        v1.z = acc[i][6] * p; v1.w = acc[i][7] * p;
        float* op = out + (size_t)token * DDIM + (size_t)tn * 128 + tx;
        *(float4*)&op[0] = v0;
        *(float4*)&op[4] = v1;
    }
}

// ---------------- diagnostics -------------------------------------------------
__global__ void diag_kernel(const float* __restrict__ x,
                            const float* __restrict__ wi,
                            const float* __restrict__ out) {
    int tid = threadIdx.x;
    size_t NH = (size_t)g_ntiles * 128 * FDIM;
    float mdH = 0.f, mxH = 0.f;
    for (size_t i = tid * 8; i < NH; i += 256 * 8 * 13) {
        float ref = g_hidden[i];
        float mv  = __bfloat162float(g_hhi[i]) + __bfloat162float(g_hlo[i]);
        float d = fabsf(mv - ref) / fmaxf(fabsf(ref), 1e-3f);
        if (d > mdH) mdH = d;
        if (fabsf(mv) > mxH) mxH = fabsf(mv);
    }
    float mdO = 0.f, mxO = 0.f;
    for (size_t i = tid * 8; i < OUT0; i += 256 * 8 * 13) {
        float ref = out[i];
        float mv  = g_out_mma[i];
        float d = fabsf(mv - ref) / fmaxf(fabsf(ref), 1e-3f);
        if (d > mdO) mdO = d;
        if (fabsf(mv) > mxO) mxO = fabsf(mv);
    }
    atomic_fmax(&g_diag[0], mdH);
    atomic_fmax(&g_diag[1], mxH);
    atomic_fmax(&g_diag[2], mdO);
    atomic_fmax(&g_diag[3], mxO);
    __syncthreads();
    if (tid == 0) {
        float xc = __bfloat162float(g_xhi[5]) + __bfloat162float(g_xlo[5]);
        float wr = wi[(size_t)3 * FDIM + 7];   // w_in[0][d=3][f=7]
        float wc = __bfloat162float(g_w1hi[(size_t)7 * DDIM + 3]) +
                   __bfloat162float(g_w1lo[(size_t)7 * DDIM + 3]);
        size_t hi_ = (size_t)123 * FDIM + 456;
        float hr = g_hidden[hi_];
        float hc = __bfloat162float(g_hhi[hi_]) + __bfloat162float(g_hlo[hi_]);
        printf("DIAG nt=%d Hmd=%e Hmax=%e Omd=%e Omax=%e | x5=%e/%e w=%e/%e h=%e/%e o999=%e/%e\n",
               g_ntiles, g_diag[0], g_diag[1], g_diag[2], g_diag[3],
               x[5], xc, wr, wc, hr, hc, out[999], g_out_mma[999]);
    }
}

// ---------------- launch ------------------------------------------------------
extern "C" void kernel_launch(void* const* d_in, const int* in_sizes, int n_in,
                              void* d_out, int out_size) {
    const float* x  = (const float*)d_in[0];
    const float* rw = (const float*)d_in[1];
    const float* wi = (const float*)d_in[2];   // [E,D,F]
    const float* wo = (const float*)d_in[3];   // [E,F,D]
    float* out = (float*)d_out;

    int aux = ((size_t)out_size >= OUT1 + TOK) ? 1 : 0;

    reset_kernel<<<1, 32>>>();
    router_kernel<<<(TOK * 32 + 255) / 256, 256>>>(x, rw, out, aux);
    build_kernel<<<1, 256>>>();
    scatter_kernel<<<(TOK + 255) / 256, 256>>>();

    // mma pipeline -> scratch
    conv_x_kernel<<<(TOK * DDIM / 4 + 255) / 256, 256>>>(x);
    conv_wt_kernel<<<dim3(FDIM / 32, DDIM / 32, NEXP), dim3(32, 8)>>>(wi, g_w1hi, g_w1lo, DDIM, FDIM);
    conv_wt_kernel<<<dim3(DDIM / 32, FDIM / 32, NEXP), dim3(32, 8)>>>(wo, g_w2hi, g_w2lo, FDIM, DDIM);
    gemm1_mma<<<dim3(FDIM / 128, MAXTILES), 256>>>();
    gemm2_mma<<<dim3(DDIM / 128, MAXTILES), 256>>>(g_out_mma);

    // known-good fp32 path -> out
    gemm1_f32<<<dim3(FDIM / 128, MAXTILES), 256>>>(x, wi);
    gemm2_f32<<<dim3(DDIM / 128, MAXTILES), 256>>>(wo, out);

    diag_kernel<<<1, 256>>>(x, wi, out);
}